// round 5
// baseline (speedup 1.0000x reference)
#include <cuda_runtime.h>

#define EPSF 1e-8f
#define BMAX 32
#define BNMAX (32 * 4096)

// -------- scratch (allocation-free: __device__ globals) --------
__device__ float g_cs1[BNMAX];
__device__ float g_cs2[BNMAX];
__device__ float g_alp[BNMAX];
__device__ float g_cs4[BNMAX];
__device__ float g_s1[BNMAX];
__device__ float g_s2[BNMAX];
__device__ float g_nrm[BNMAX];
// 0=fn_addr 1=arg_addr 2=param_addr 3=body_addr 4=a_tag 5=a_l 6=a_r 7=b_tag 8=b_l 9=b_r
__device__ float g_vec[10][BMAX][128];

// -------- helpers --------
__device__ __forceinline__ float wsum(float v) {
#pragma unroll
    for (int m = 16; m > 0; m >>= 1) v += __shfl_xor_sync(0xffffffffu, v, m);
    return v;
}
__device__ __forceinline__ float dot4(const float4& a, const float4& b) {
    return a.x * b.x + a.y * b.y + a.z * b.z + a.w * b.w;
}
__device__ __forceinline__ void acc4(float4& acc, float s, const float4& v) {
    acc.x += s * v.x; acc.y += s * v.y; acc.z += s * v.z; acc.w += s * v.w;
}
__device__ __forceinline__ float4 mix4(float wa, const float4& a, float wb, const float4& b) {
    return make_float4(wa * a.x + wb * b.x, wa * a.y + wb * b.y,
                       wa * a.z + wb * b.z, wa * a.w + wb * b.w);
}

__global__ void k_zero() {
    int i = blockIdx.x * blockDim.x + threadIdx.x;
    if (i < 10 * BMAX * 128) (&g_vec[0][0][0])[i] = 0.f;
}

// ============ K0: cs1 = cos(at, addr); fn += cs1*c1; arg += cs1*c2; store ||addr row|| ============
__global__ void __launch_bounds__(256) k_stage0(
    const float* __restrict__ at, const float* __restrict__ addr,
    const float* __restrict__ c1, const float* __restrict__ c2, int N)
{
    const int b = blockIdx.y;
    const int lane = threadIdx.x & 31;
    const int wid = threadIdx.x >> 5;
    const int sub = lane & 7, grp = lane >> 3;
    __shared__ float4 sq[32];
    float4 q = reinterpret_cast<const float4*>(at)[b * 32 + lane];
    if (wid == 0) sq[lane] = q;
    float nq = sqrtf(wsum(dot4(q, q)));
    __syncthreads();

    const float4* addr4 = reinterpret_cast<const float4*>(addr);
    const float4* c14 = reinterpret_cast<const float4*>(c1);
    const float4* c24 = reinterpret_cast<const float4*>(c2);
    float4 af = make_float4(0,0,0,0), aa = make_float4(0,0,0,0);
    int row0 = blockIdx.x * 64;
    int rend = min(row0 + 64, N);
    for (int rr = row0 + wid * 4; rr < rend; rr += 32) {
        int myrow = rr + grp;
        size_t rb = ((size_t)(b * N + myrow)) * 32;
        float dq = 0.f, na = 0.f;
#pragma unroll
        for (int j = 0; j < 4; j++) {
            float4 av = addr4[rb + sub * 4 + j];
            dq += dot4(av, sq[sub * 4 + j]);
            na += dot4(av, av);
        }
#pragma unroll
        for (int m = 4; m > 0; m >>= 1) {
            dq += __shfl_xor_sync(0xffffffffu, dq, m);
            na += __shfl_xor_sync(0xffffffffu, na, m);
        }
        na = sqrtf(na);
        float cs = dq / fmaxf(na * nq, EPSF);
        if (sub == 0) { g_cs1[b * N + myrow] = cs; g_nrm[b * N + myrow] = na; }
#pragma unroll
        for (int i = 0; i < 4; i++) {
            float w = __shfl_sync(0xffffffffu, cs, i * 8);
            size_t off = ((size_t)(b * N + rr + i)) * 32 + lane;
            acc4(af, w, c14[off]);
            acc4(aa, w, c24[off]);
        }
    }
    __shared__ float sf[128], sa[128];
    if (threadIdx.x < 128) { sf[threadIdx.x] = 0.f; sa[threadIdx.x] = 0.f; }
    __syncthreads();
    int base = lane * 4;
    atomicAdd(&sf[base + 0], af.x); atomicAdd(&sf[base + 1], af.y);
    atomicAdd(&sf[base + 2], af.z); atomicAdd(&sf[base + 3], af.w);
    atomicAdd(&sa[base + 0], aa.x); atomicAdd(&sa[base + 1], aa.y);
    atomicAdd(&sa[base + 2], aa.z); atomicAdd(&sa[base + 3], aa.w);
    __syncthreads();
    if (threadIdx.x < 128) {
        atomicAdd(&g_vec[0][b][threadIdx.x], sf[threadIdx.x]);
        atomicAdd(&g_vec[1][b][threadIdx.x], sa[threadIdx.x]);
    }
}

// ============ K1: cs2=cos(fn,·), cs3=cos(arg,·); 5 weighted sums ============
__global__ void __launch_bounds__(256) k_stage1(
    const float* __restrict__ addr, const float* __restrict__ tg,
    const float* __restrict__ c1, const float* __restrict__ c2, int N)
{
    const int b = blockIdx.y;
    const int lane = threadIdx.x & 31;
    const int wid = threadIdx.x >> 5;
    const int sub = lane & 7, grp = lane >> 3;
    __shared__ float4 sqf[32], sqa[32];
    float4 qf = reinterpret_cast<const float4*>(&g_vec[0][b][0])[lane];
    float4 qa = reinterpret_cast<const float4*>(&g_vec[1][b][0])[lane];
    if (wid == 0) { sqf[lane] = qf; sqa[lane] = qa; }
    float nf  = sqrtf(wsum(dot4(qf, qf)));
    float nag = sqrtf(wsum(dot4(qa, qa)));
    __syncthreads();

    const float4* addr4 = reinterpret_cast<const float4*>(addr);
    const float4* tg4 = reinterpret_cast<const float4*>(tg);
    const float4* c14 = reinterpret_cast<const float4*>(c1);
    const float4* c24 = reinterpret_cast<const float4*>(c2);
    float4 aP = make_float4(0,0,0,0), aB = make_float4(0,0,0,0);
    float4 aT = make_float4(0,0,0,0), aL = make_float4(0,0,0,0), aR = make_float4(0,0,0,0);
    int row0 = blockIdx.x * 64;
    int rend = min(row0 + 64, N);
    for (int rr = row0 + wid * 4; rr < rend; rr += 32) {
        int myrow = rr + grp;
        size_t rb = ((size_t)(b * N + myrow)) * 32;
        float df = 0.f, da = 0.f;
#pragma unroll
        for (int j = 0; j < 4; j++) {
            float4 av = addr4[rb + sub * 4 + j];
            df += dot4(av, sqf[sub * 4 + j]);
            da += dot4(av, sqa[sub * 4 + j]);
        }
#pragma unroll
        for (int m = 4; m > 0; m >>= 1) {
            df += __shfl_xor_sync(0xffffffffu, df, m);
            da += __shfl_xor_sync(0xffffffffu, da, m);
        }
        float nr = g_nrm[b * N + myrow];
        float cs2 = df / fmaxf(nr * nf, EPSF);
        float cs3 = da / fmaxf(nr * nag, EPSF);
        if (sub == 0) g_cs2[b * N + myrow] = cs2;
#pragma unroll
        for (int i = 0; i < 4; i++) {
            float w2 = __shfl_sync(0xffffffffu, cs2, i * 8);
            float w3 = __shfl_sync(0xffffffffu, cs3, i * 8);
            size_t off = ((size_t)(b * N + rr + i)) * 32 + lane;
            float4 vt = tg4[off];
            float4 v1 = c14[off];
            float4 v2 = c24[off];
            acc4(aT, w3, vt);
            acc4(aP, w2, v1); acc4(aL, w3, v1);
            acc4(aB, w2, v2); acc4(aR, w3, v2);
        }
    }
    __shared__ float s[5][128];
    for (int j = threadIdx.x; j < 5 * 128; j += 256) (&s[0][0])[j] = 0.f;
    __syncthreads();
    int base = lane * 4;
    atomicAdd(&s[0][base+0], aP.x); atomicAdd(&s[0][base+1], aP.y); atomicAdd(&s[0][base+2], aP.z); atomicAdd(&s[0][base+3], aP.w);
    atomicAdd(&s[1][base+0], aB.x); atomicAdd(&s[1][base+1], aB.y); atomicAdd(&s[1][base+2], aB.z); atomicAdd(&s[1][base+3], aB.w);
    atomicAdd(&s[2][base+0], aT.x); atomicAdd(&s[2][base+1], aT.y); atomicAdd(&s[2][base+2], aT.z); atomicAdd(&s[2][base+3], aT.w);
    atomicAdd(&s[3][base+0], aL.x); atomicAdd(&s[3][base+1], aL.y); atomicAdd(&s[3][base+2], aL.z); atomicAdd(&s[3][base+3], aL.w);
    atomicAdd(&s[4][base+0], aR.x); atomicAdd(&s[4][base+1], aR.y); atomicAdd(&s[4][base+2], aR.z); atomicAdd(&s[4][base+3], aR.w);
    __syncthreads();
    if (threadIdx.x < 128) {
        atomicAdd(&g_vec[2][b][threadIdx.x], s[0][threadIdx.x]);
        atomicAdd(&g_vec[3][b][threadIdx.x], s[1][threadIdx.x]);
        atomicAdd(&g_vec[4][b][threadIdx.x], s[2][threadIdx.x]);
        atomicAdd(&g_vec[5][b][threadIdx.x], s[3][threadIdx.x]);
        atomicAdd(&g_vec[6][b][threadIdx.x], s[4][threadIdx.x]);
    }
}

// ============ K2: flattened insert(param)+replace+select(body), 8-lane groups ============
__global__ void __launch_bounds__(256) k_stage2(
    const float* __restrict__ addr, const float* __restrict__ tg,
    const float* __restrict__ c1, const float* __restrict__ c2, int N)
{
    const int b = blockIdx.y;
    const int lane = threadIdx.x & 31;
    const int wid = threadIdx.x >> 5;
    const int sub = lane & 7, grp = lane >> 3;
    __shared__ float4 sqp[32], sqb[32], sqal[32], sqar[32];
    float4 qp  = reinterpret_cast<const float4*>(&g_vec[2][b][0])[lane];
    float4 qb  = reinterpret_cast<const float4*>(&g_vec[3][b][0])[lane];
    float4 qal = reinterpret_cast<const float4*>(&g_vec[5][b][0])[lane];
    float4 qar = reinterpret_cast<const float4*>(&g_vec[6][b][0])[lane];
    if (wid == 0) { sqp[lane] = qp; sqb[lane] = qb; sqal[lane] = qal; sqar[lane] = qar; }
    // per-batch constants
    float np    = sqrtf(wsum(dot4(qp, qp)));
    float nb    = sqrtf(wsum(dot4(qb, qb)));
    float kalp  = wsum(dot4(qal, qp));
    float karp  = wsum(dot4(qar, qp));
    float kalal = wsum(dot4(qal, qal));
    float karar = wsum(dot4(qar, qar));
    __syncthreads();

    const float4* addr4 = reinterpret_cast<const float4*>(addr);
    const float4* tg4 = reinterpret_cast<const float4*>(tg);
    const float4* c14 = reinterpret_cast<const float4*>(c1);
    const float4* c24 = reinterpret_cast<const float4*>(c2);

    float4 At = make_float4(0,0,0,0), A1 = make_float4(0,0,0,0), A2 = make_float4(0,0,0,0);
    float St = 0.f, S1al = 0.f, S1g = 0.f, S2ar = 0.f, S2g = 0.f;

    int row0 = blockIdx.x * 64;
    int rend = min(row0 + 64, N);
    for (int rr = row0 + wid * 4; rr < rend; rr += 32) {
        int myrow = rr + grp;
        size_t rb = ((size_t)(b * N + myrow)) * 32;
        float dp=0.f, db=0.f, d1p=0.f, x1=0.f, n1=0.f, d2p=0.f, x2=0.f, n2=0.f;
#pragma unroll
        for (int j = 0; j < 4; j++) {
            int qi = sub * 4 + j;
            float4 av  = addr4[rb + qi];
            float4 v1v = c14[rb + qi];
            float4 v2v = c24[rb + qi];
            float4 qpj = sqp[qi], qbj = sqb[qi], qalj = sqal[qi], qarj = sqar[qi];
            dp  += dot4(av, qpj);  db += dot4(av, qbj);
            d1p += dot4(v1v, qpj); x1 += dot4(v1v, qalj); n1 += dot4(v1v, v1v);
            d2p += dot4(v2v, qpj); x2 += dot4(v2v, qarj); n2 += dot4(v2v, v2v);
        }
#pragma unroll
        for (int m = 4; m > 0; m >>= 1) {
            dp  += __shfl_xor_sync(0xffffffffu, dp, m);
            db  += __shfl_xor_sync(0xffffffffu, db, m);
            d1p += __shfl_xor_sync(0xffffffffu, d1p, m);
            x1  += __shfl_xor_sync(0xffffffffu, x1, m);
            n1  += __shfl_xor_sync(0xffffffffu, n1, m);
            d2p += __shfl_xor_sync(0xffffffffu, d2p, m);
            x2  += __shfl_xor_sync(0xffffffffu, x2, m);
            n2  += __shfl_xor_sync(0xffffffffu, n2, m);
        }
        float nr = g_nrm[b * N + myrow];
        float alr = dp / fmaxf(nr * np, EPSF);
        float alpha = (alr > EPSF) ? alr : 0.f;
        float ia = 1.f - alpha;
        float cs4 = db / fmaxf(nr * nb, EPSF);
        float du1 = ia * d1p + alpha * kalp;
        float nu1 = sqrtf(fmaxf(ia*ia*n1 + 2.f*ia*alpha*x1 + alpha*alpha*kalal, 0.f));
        float s1 = du1 / fmaxf(nu1 * np, EPSF);
        float du2 = ia * d2p + alpha * karp;
        float nu2 = sqrtf(fmaxf(ia*ia*n2 + 2.f*ia*alpha*x2 + alpha*alpha*karar, 0.f));
        float s2 = du2 / fmaxf(nu2 * np, EPSF);
        float wt = cs4 * ia;
        float w1 = cs4 * (1.f - s1) * ia;
        float w2 = cs4 * (1.f - s2) * ia;
        if (sub == 0) {
            int bn = b * N + myrow;
            g_alp[bn] = alpha; g_s1[bn] = s1; g_s2[bn] = s2; g_cs4[bn] = cs4;
            St   += cs4 * alpha;
            S1al += cs4 * (1.f - s1) * alpha;
            S1g  += cs4 * s1;
            S2ar += cs4 * (1.f - s2) * alpha;
            S2g  += cs4 * s2;
        }
#pragma unroll
        for (int i = 0; i < 4; i++) {
            float bwt = __shfl_sync(0xffffffffu, wt, i * 8);
            float bw1 = __shfl_sync(0xffffffffu, w1, i * 8);
            float bw2 = __shfl_sync(0xffffffffu, w2, i * 8);
            size_t off = ((size_t)(b * N + rr + i)) * 32 + lane;
            float4 vt = tg4[off];
            float4 v1 = c14[off];   // L1 hit
            float4 v2 = c24[off];   // L1 hit
            acc4(At, bwt, vt);
            acc4(A1, bw1, v1);
            acc4(A2, bw2, v2);
        }
    }
    // fold scalar sums (only sub==0 lanes hold partials; full-warp sum is exact)
    St = wsum(St); S1al = wsum(S1al); S1g = wsum(S1g); S2ar = wsum(S2ar); S2g = wsum(S2g);
    float4 qtag = reinterpret_cast<const float4*>(&g_vec[4][b][0])[lane];
    float4 qarg = reinterpret_cast<const float4*>(&g_vec[1][b][0])[lane];
    acc4(At, St, qtag);
    acc4(A1, S1al, qal); acc4(A1, S1g, qarg);
    acc4(A2, S2ar, qar); acc4(A2, S2g, qarg);

    __shared__ float s[3][128];
    for (int j = threadIdx.x; j < 3 * 128; j += 256) (&s[0][0])[j] = 0.f;
    __syncthreads();
    int base = lane * 4;
    atomicAdd(&s[0][base+0], At.x); atomicAdd(&s[0][base+1], At.y); atomicAdd(&s[0][base+2], At.z); atomicAdd(&s[0][base+3], At.w);
    atomicAdd(&s[1][base+0], A1.x); atomicAdd(&s[1][base+1], A1.y); atomicAdd(&s[1][base+2], A1.z); atomicAdd(&s[1][base+3], A1.w);
    atomicAdd(&s[2][base+0], A2.x); atomicAdd(&s[2][base+1], A2.y); atomicAdd(&s[2][base+2], A2.z); atomicAdd(&s[2][base+3], A2.w);
    __syncthreads();
    if (threadIdx.x < 128) {
        atomicAdd(&g_vec[7][b][threadIdx.x], s[0][threadIdx.x]);
        atomicAdd(&g_vec[8][b][threadIdx.x], s[1][threadIdx.x]);
        atomicAdd(&g_vec[9][b][threadIdx.x], s[2][threadIdx.x]);
    }
}

// ============ K3: reconstruct rows + insert(at, b_*) + closed-form GC ============
__global__ void __launch_bounds__(256) k_stage3(
    const float* __restrict__ tg, const float* __restrict__ c1, const float* __restrict__ c2,
    const float* __restrict__ zv, const int* __restrict__ gsp,
    float* __restrict__ ot, float* __restrict__ o1, float* __restrict__ o2,
    int B, int N)
{
    int i = blockIdx.x * blockDim.x + threadIdx.x;
    int total = B * N * 32;
    if (i >= total) return;
    int d4 = i & 31;
    int bn = i >> 5;
    int b = bn / N;
    float a1 = g_cs1[bn]; a1 = (a1 > EPSF) ? a1 : 0.f;
    float cf = g_cs2[bn]; cf = (cf > EPSF) ? cf : 0.f;
    float cp = g_alp[bn];
    float cb = g_cs4[bn]; cb = (cb > EPSF) ? cb : 0.f;
    float s1 = g_s1[bn], s2 = g_s2[bn];
    float base = (1.f - cf) * (1.f - cp) * (1.f - cb);
    int g = *gsp;
    float P = 1.f;
    for (int k = 0; k < g; k++) P *= base;
    float ia1 = 1.f - a1, icp = 1.f - cp, iP = 1.f - P;
    float4 z    = reinterpret_cast<const float4*>(zv)[d4];
    float4 qarg = reinterpret_cast<const float4*>(&g_vec[1][b][0])[d4];
    float4 qtag = reinterpret_cast<const float4*>(&g_vec[4][b][0])[d4];
    float4 qal  = reinterpret_cast<const float4*>(&g_vec[5][b][0])[d4];
    float4 qar  = reinterpret_cast<const float4*>(&g_vec[6][b][0])[d4];
    float4 bt   = reinterpret_cast<const float4*>(&g_vec[7][b][0])[d4];
    float4 bl   = reinterpret_cast<const float4*>(&g_vec[8][b][0])[d4];
    float4 br   = reinterpret_cast<const float4*>(&g_vec[9][b][0])[d4];

    float4 t = reinterpret_cast<const float4*>(tg)[i];
    t = mix4(icp, t, cp, qtag);
    t = mix4(ia1, t, a1, bt);
    reinterpret_cast<float4*>(ot)[i] = mix4(P, t, iP, z);

    t = reinterpret_cast<const float4*>(c1)[i];
    t = mix4(icp, t, cp, qal);
    t = mix4(1.f - s1, t, s1, qarg);
    t = mix4(ia1, t, a1, bl);
    reinterpret_cast<float4*>(o1)[i] = mix4(P, t, iP, z);

    t = reinterpret_cast<const float4*>(c2)[i];
    t = mix4(icp, t, cp, qar);
    t = mix4(1.f - s2, t, s2, qarg);
    t = mix4(ia1, t, a1, br);
    reinterpret_cast<float4*>(o2)[i] = mix4(P, t, iP, z);
}

// ============ launch ============
extern "C" void kernel_launch(void* const* d_in, const int* in_sizes, int n_in,
                              void* d_out, int out_size)
{
    const float* at   = (const float*)d_in[0];
    const float* addr = (const float*)d_in[1];
    const float* tg   = (const float*)d_in[2];
    const float* c1   = (const float*)d_in[3];
    const float* c2   = (const float*)d_in[4];
    const float* zv   = (const float*)d_in[5];
    const int*   gs   = (const int*)d_in[6];

    int D = in_sizes[5];
    int B = in_sizes[0] / D;
    int N = in_sizes[1] / in_sizes[0];

    size_t stride = (size_t)B * N * D;
    float* ot = (float*)d_out;
    float* o1 = ot + stride;
    float* o2 = o1 + stride;

    k_zero<<<(10 * BMAX * 128 + 255) / 256, 256>>>();

    dim3 grid((N + 63) / 64, B);
    k_stage0<<<grid, 256>>>(at, addr, c1, c2, N);
    k_stage1<<<grid, 256>>>(addr, tg, c1, c2, N);
    k_stage2<<<grid, 256>>>(addr, tg, c1, c2, N);

    int tot4 = B * N * (D / 4);
    k_stage3<<<(tot4 + 255) / 256, 256>>>(tg, c1, c2, zv, gs, ot, o1, o2, B, N);

    (void)n_in; (void)out_size;
}

// round 6
// speedup vs baseline: 1.2570x; 1.2570x over previous
#include <cuda_runtime.h>

#define EPSF 1e-8f
#define BMAX 32
#define BNMAX (32 * 4096)

// -------- scratch (allocation-free: __device__ globals) --------
__device__ float g_cs1[BNMAX];
__device__ float g_cs2[BNMAX];
__device__ float g_alp[BNMAX];
__device__ float g_cs4[BNMAX];
__device__ float g_s1[BNMAX];
__device__ float g_s2[BNMAX];
__device__ float g_nrm[BNMAX];
// 0=fn_addr 1=arg_addr 2=param_addr 3=body_addr 4=a_tag 5=a_l 6=a_r 7=b_tag 8=b_l 9=b_r
__device__ float g_vec[10][BMAX][128];

// -------- helpers --------
__device__ __forceinline__ float wsum(float v) {
#pragma unroll
    for (int m = 16; m > 0; m >>= 1) v += __shfl_xor_sync(0xffffffffu, v, m);
    return v;
}
__device__ __forceinline__ float dot4(const float4& a, const float4& b) {
    return a.x * b.x + a.y * b.y + a.z * b.z + a.w * b.w;
}
__device__ __forceinline__ void acc4(float4& acc, float s, const float4& v) {
    acc.x += s * v.x; acc.y += s * v.y; acc.z += s * v.z; acc.w += s * v.w;
}
__device__ __forceinline__ float4 mix4(float wa, const float4& a, float wb, const float4& b) {
    return make_float4(wa * a.x + wb * b.x, wa * a.y + wb * b.y,
                       wa * a.z + wb * b.z, wa * a.w + wb * b.w);
}
// fast guarded cosine divide: num / max(den, eps)
__device__ __forceinline__ float fdivg(float num, float den) {
    return __fdividef(num, fmaxf(den, EPSF));
}

__global__ void k_zero() {
    int i = blockIdx.x * blockDim.x + threadIdx.x;
    if (i < 10 * BMAX * 128) (&g_vec[0][0][0])[i] = 0.f;
}

// ============ K0: cs1 = cos(at, addr); fn += cs1*c1; arg += cs1*c2; store ||addr row|| ============
__global__ void __launch_bounds__(256, 4) k_stage0(
    const float* __restrict__ at, const float* __restrict__ addr,
    const float* __restrict__ c1, const float* __restrict__ c2, int N)
{
    const int b = blockIdx.y;
    const int lane = threadIdx.x & 31;
    const int w = threadIdx.x >> 5;
    float4 q = reinterpret_cast<const float4*>(at)[b * 32 + lane];
    float nq = sqrtf(wsum(dot4(q, q)));
    float4 af = make_float4(0, 0, 0, 0), aa = make_float4(0, 0, 0, 0);
    int row0 = blockIdx.x * 64;
    int rend = min(row0 + 64, N);
#pragma unroll 2
    for (int r = row0 + w; r < rend; r += 8) {
        size_t off = ((size_t)(b * N + r)) * 32 + lane;
        float4 a  = reinterpret_cast<const float4*>(addr)[off];
        float4 v1 = reinterpret_cast<const float4*>(c1)[off];
        float4 v2 = reinterpret_cast<const float4*>(c2)[off];
        float dq = wsum(dot4(a, q));
        float na = sqrtf(wsum(dot4(a, a)));
        float cs = fdivg(dq, na * nq);
        if (lane == 0) { g_cs1[b * N + r] = cs; g_nrm[b * N + r] = na; }
        acc4(af, cs, v1);
        acc4(aa, cs, v2);
    }
    __shared__ float sf[128], sa[128];
    if (threadIdx.x < 128) { sf[threadIdx.x] = 0.f; sa[threadIdx.x] = 0.f; }
    __syncthreads();
    int base = lane * 4;
    atomicAdd(&sf[base + 0], af.x); atomicAdd(&sf[base + 1], af.y);
    atomicAdd(&sf[base + 2], af.z); atomicAdd(&sf[base + 3], af.w);
    atomicAdd(&sa[base + 0], aa.x); atomicAdd(&sa[base + 1], aa.y);
    atomicAdd(&sa[base + 2], aa.z); atomicAdd(&sa[base + 3], aa.w);
    __syncthreads();
    if (threadIdx.x < 128) {
        atomicAdd(&g_vec[0][b][threadIdx.x], sf[threadIdx.x]);
        atomicAdd(&g_vec[1][b][threadIdx.x], sa[threadIdx.x]);
    }
}

// ============ K1: cs2=cos(fn,·), cs3=cos(arg,·); 5 weighted sums ============
__global__ void __launch_bounds__(256, 4) k_stage1(
    const float* __restrict__ addr, const float* __restrict__ tg,
    const float* __restrict__ c1, const float* __restrict__ c2, int N)
{
    const int b = blockIdx.y;
    const int lane = threadIdx.x & 31;
    const int w = threadIdx.x >> 5;
    float4 qf = reinterpret_cast<const float4*>(&g_vec[0][b][0])[lane];
    float4 qa = reinterpret_cast<const float4*>(&g_vec[1][b][0])[lane];
    float nf  = sqrtf(wsum(dot4(qf, qf)));
    float nag = sqrtf(wsum(dot4(qa, qa)));
    float4 aP = make_float4(0,0,0,0), aB = make_float4(0,0,0,0);
    float4 aT = make_float4(0,0,0,0), aL = make_float4(0,0,0,0), aR = make_float4(0,0,0,0);
    int row0 = blockIdx.x * 64;
    int rend = min(row0 + 64, N);
#pragma unroll 2
    for (int r = row0 + w; r < rend; r += 8) {
        size_t off = ((size_t)(b * N + r)) * 32 + lane;
        float4 a  = reinterpret_cast<const float4*>(addr)[off];
        float4 vt = reinterpret_cast<const float4*>(tg)[off];
        float4 v1 = reinterpret_cast<const float4*>(c1)[off];
        float4 v2 = reinterpret_cast<const float4*>(c2)[off];
        float nr = g_nrm[b * N + r];
        float df = wsum(dot4(a, qf));
        float da = wsum(dot4(a, qa));
        float cs2 = fdivg(df, nr * nf);
        float cs3 = fdivg(da, nr * nag);
        if (lane == 0) g_cs2[b * N + r] = cs2;
        acc4(aT, cs3, vt);
        acc4(aP, cs2, v1); acc4(aL, cs3, v1);
        acc4(aB, cs2, v2); acc4(aR, cs3, v2);
    }
    __shared__ float s[5][128];
    for (int j = threadIdx.x; j < 5 * 128; j += 256) (&s[0][0])[j] = 0.f;
    __syncthreads();
    int base = lane * 4;
    atomicAdd(&s[0][base+0], aP.x); atomicAdd(&s[0][base+1], aP.y); atomicAdd(&s[0][base+2], aP.z); atomicAdd(&s[0][base+3], aP.w);
    atomicAdd(&s[1][base+0], aB.x); atomicAdd(&s[1][base+1], aB.y); atomicAdd(&s[1][base+2], aB.z); atomicAdd(&s[1][base+3], aB.w);
    atomicAdd(&s[2][base+0], aT.x); atomicAdd(&s[2][base+1], aT.y); atomicAdd(&s[2][base+2], aT.z); atomicAdd(&s[2][base+3], aT.w);
    atomicAdd(&s[3][base+0], aL.x); atomicAdd(&s[3][base+1], aL.y); atomicAdd(&s[3][base+2], aL.z); atomicAdd(&s[3][base+3], aL.w);
    atomicAdd(&s[4][base+0], aR.x); atomicAdd(&s[4][base+1], aR.y); atomicAdd(&s[4][base+2], aR.z); atomicAdd(&s[4][base+3], aR.w);
    __syncthreads();
    if (threadIdx.x < 128) {
        atomicAdd(&g_vec[2][b][threadIdx.x], s[0][threadIdx.x]);
        atomicAdd(&g_vec[3][b][threadIdx.x], s[1][threadIdx.x]);
        atomicAdd(&g_vec[4][b][threadIdx.x], s[2][threadIdx.x]);
        atomicAdd(&g_vec[5][b][threadIdx.x], s[3][threadIdx.x]);
        atomicAdd(&g_vec[6][b][threadIdx.x], s[4][threadIdx.x]);
    }
}

// ============ K2: flattened insert(param)+replace+select(body) ============
__global__ void __launch_bounds__(256, 4) k_stage2(
    const float* __restrict__ addr, const float* __restrict__ tg,
    const float* __restrict__ c1, const float* __restrict__ c2, int N)
{
    const int b = blockIdx.y;
    const int lane = threadIdx.x & 31;
    const int w = threadIdx.x >> 5;
    float4 qp  = reinterpret_cast<const float4*>(&g_vec[2][b][0])[lane];
    float4 qb  = reinterpret_cast<const float4*>(&g_vec[3][b][0])[lane];
    float4 qal = reinterpret_cast<const float4*>(&g_vec[5][b][0])[lane];
    float4 qar = reinterpret_cast<const float4*>(&g_vec[6][b][0])[lane];
    // per-batch constants (one-time prologue reductions)
    float np    = sqrtf(wsum(dot4(qp, qp)));
    float nb    = sqrtf(wsum(dot4(qb, qb)));
    float kalp  = wsum(dot4(qal, qp));
    float karp  = wsum(dot4(qar, qp));
    float kalal = wsum(dot4(qal, qal));
    float karar = wsum(dot4(qar, qar));

    float4 At = make_float4(0,0,0,0), A1 = make_float4(0,0,0,0), A2 = make_float4(0,0,0,0);
    float St = 0.f, S1al = 0.f, S1g = 0.f, S2ar = 0.f, S2g = 0.f;

    int row0 = blockIdx.x * 64;
    int rend = min(row0 + 64, N);
#pragma unroll 2
    for (int r = row0 + w; r < rend; r += 8) {
        size_t off = ((size_t)(b * N + r)) * 32 + lane;
        float4 a  = reinterpret_cast<const float4*>(addr)[off];
        float4 vt = reinterpret_cast<const float4*>(tg)[off];
        float4 v1 = reinterpret_cast<const float4*>(c1)[off];
        float4 v2 = reinterpret_cast<const float4*>(c2)[off];
        // 8 independent single-level reductions
        float dp  = wsum(dot4(a, qp));
        float db  = wsum(dot4(a, qb));
        float d1p = wsum(dot4(v1, qp));
        float x1  = wsum(dot4(v1, qal));
        float n1  = wsum(dot4(v1, v1));
        float d2p = wsum(dot4(v2, qp));
        float x2  = wsum(dot4(v2, qar));
        float n2  = wsum(dot4(v2, v2));

        float nr = g_nrm[b * N + r];
        float alr = fdivg(dp, nr * np);
        float alpha = (alr > EPSF) ? alr : 0.f;
        float ia = 1.f - alpha;
        float cs4 = fdivg(db, nr * nb);

        float du1 = ia * d1p + alpha * kalp;
        float nu1 = sqrtf(fmaxf(ia*ia*n1 + 2.f*ia*alpha*x1 + alpha*alpha*kalal, 0.f));
        float s1 = fdivg(du1, nu1 * np);
        float du2 = ia * d2p + alpha * karp;
        float nu2 = sqrtf(fmaxf(ia*ia*n2 + 2.f*ia*alpha*x2 + alpha*alpha*karar, 0.f));
        float s2 = fdivg(du2, nu2 * np);

        if (lane == 0) {
            int bn = b * N + r;
            g_alp[bn] = alpha; g_s1[bn] = s1; g_s2[bn] = s2; g_cs4[bn] = cs4;
        }
        float w1 = cs4 * (1.f - s1) * ia;
        float w2 = cs4 * (1.f - s2) * ia;
        acc4(At, cs4 * ia, vt);
        acc4(A1, w1, v1);
        acc4(A2, w2, v2);
        St   += cs4 * alpha;
        S1al += cs4 * (1.f - s1) * alpha;
        S1g  += cs4 * s1;
        S2ar += cs4 * (1.f - s2) * alpha;
        S2g  += cs4 * s2;
    }
    // epilogue: fold in q-vector terms
    float4 qtag = reinterpret_cast<const float4*>(&g_vec[4][b][0])[lane];
    float4 qarg = reinterpret_cast<const float4*>(&g_vec[1][b][0])[lane];
    acc4(At, St, qtag);
    acc4(A1, S1al, qal); acc4(A1, S1g, qarg);
    acc4(A2, S2ar, qar); acc4(A2, S2g, qarg);

    __shared__ float s[3][128];
    for (int j = threadIdx.x; j < 3 * 128; j += 256) (&s[0][0])[j] = 0.f;
    __syncthreads();
    int base = lane * 4;
    atomicAdd(&s[0][base+0], At.x); atomicAdd(&s[0][base+1], At.y); atomicAdd(&s[0][base+2], At.z); atomicAdd(&s[0][base+3], At.w);
    atomicAdd(&s[1][base+0], A1.x); atomicAdd(&s[1][base+1], A1.y); atomicAdd(&s[1][base+2], A1.z); atomicAdd(&s[1][base+3], A1.w);
    atomicAdd(&s[2][base+0], A2.x); atomicAdd(&s[2][base+1], A2.y); atomicAdd(&s[2][base+2], A2.z); atomicAdd(&s[2][base+3], A2.w);
    __syncthreads();
    if (threadIdx.x < 128) {
        atomicAdd(&g_vec[7][b][threadIdx.x], s[0][threadIdx.x]);
        atomicAdd(&g_vec[8][b][threadIdx.x], s[1][threadIdx.x]);
        atomicAdd(&g_vec[9][b][threadIdx.x], s[2][threadIdx.x]);
    }
}

// ============ K3: reconstruct rows + insert(at, b_*) + closed-form GC ============
__global__ void __launch_bounds__(256) k_stage3(
    const float* __restrict__ tg, const float* __restrict__ c1, const float* __restrict__ c2,
    const float* __restrict__ zv, const int* __restrict__ gsp,
    float* __restrict__ ot, float* __restrict__ o1, float* __restrict__ o2,
    int B, int N)
{
    int i = blockIdx.x * blockDim.x + threadIdx.x;
    int total = B * N * 32;
    if (i >= total) return;
    int d4 = i & 31;
    int bn = i >> 5;
    int b = bn / N;
    float a1 = g_cs1[bn]; a1 = (a1 > EPSF) ? a1 : 0.f;
    float cf = g_cs2[bn]; cf = (cf > EPSF) ? cf : 0.f;
    float cp = g_alp[bn];
    float cb = g_cs4[bn]; cb = (cb > EPSF) ? cb : 0.f;
    float s1 = g_s1[bn], s2 = g_s2[bn];
    float base = (1.f - cf) * (1.f - cp) * (1.f - cb);
    int g = *gsp;
    float P = 1.f;
    for (int k = 0; k < g; k++) P *= base;
    float ia1 = 1.f - a1, icp = 1.f - cp, iP = 1.f - P;
    float4 z    = reinterpret_cast<const float4*>(zv)[d4];
    float4 qarg = reinterpret_cast<const float4*>(&g_vec[1][b][0])[d4];
    float4 qtag = reinterpret_cast<const float4*>(&g_vec[4][b][0])[d4];
    float4 qal  = reinterpret_cast<const float4*>(&g_vec[5][b][0])[d4];
    float4 qar  = reinterpret_cast<const float4*>(&g_vec[6][b][0])[d4];
    float4 bt   = reinterpret_cast<const float4*>(&g_vec[7][b][0])[d4];
    float4 bl   = reinterpret_cast<const float4*>(&g_vec[8][b][0])[d4];
    float4 br   = reinterpret_cast<const float4*>(&g_vec[9][b][0])[d4];

    float4 t = reinterpret_cast<const float4*>(tg)[i];
    t = mix4(icp, t, cp, qtag);
    t = mix4(ia1, t, a1, bt);
    reinterpret_cast<float4*>(ot)[i] = mix4(P, t, iP, z);

    t = reinterpret_cast<const float4*>(c1)[i];
    t = mix4(icp, t, cp, qal);
    t = mix4(1.f - s1, t, s1, qarg);
    t = mix4(ia1, t, a1, bl);
    reinterpret_cast<float4*>(o1)[i] = mix4(P, t, iP, z);

    t = reinterpret_cast<const float4*>(c2)[i];
    t = mix4(icp, t, cp, qar);
    t = mix4(1.f - s2, t, s2, qarg);
    t = mix4(ia1, t, a1, br);
    reinterpret_cast<float4*>(o2)[i] = mix4(P, t, iP, z);
}

// ============ launch ============
extern "C" void kernel_launch(void* const* d_in, const int* in_sizes, int n_in,
                              void* d_out, int out_size)
{
    const float* at   = (const float*)d_in[0];
    const float* addr = (const float*)d_in[1];
    const float* tg   = (const float*)d_in[2];
    const float* c1   = (const float*)d_in[3];
    const float* c2   = (const float*)d_in[4];
    const float* zv   = (const float*)d_in[5];
    const int*   gs   = (const int*)d_in[6];

    int D = in_sizes[5];
    int B = in_sizes[0] / D;
    int N = in_sizes[1] / in_sizes[0];

    size_t stride = (size_t)B * N * D;
    float* ot = (float*)d_out;
    float* o1 = ot + stride;
    float* o2 = o1 + stride;

    k_zero<<<(10 * BMAX * 128 + 255) / 256, 256>>>();

    dim3 grid((N + 63) / 64, B);
    k_stage0<<<grid, 256>>>(at, addr, c1, c2, N);
    k_stage1<<<grid, 256>>>(addr, tg, c1, c2, N);
    k_stage2<<<grid, 256>>>(addr, tg, c1, c2, N);

    int tot4 = B * N * (D / 4);
    k_stage3<<<(tot4 + 255) / 256, 256>>>(tg, c1, c2, zv, gs, ot, o1, o2, B, N);

    (void)n_in; (void)out_size;
}